// round 1
// baseline (speedup 1.0000x reference)
#include <cuda_runtime.h>
#include <cuda_bf16.h>
#include <mma.h>
#include <math.h>

namespace wm = nvcuda::wmma;
using bf16 = __nv_bfloat16;

// ---------------------------------------------------------------------------
// Problem constants
// ---------------------------------------------------------------------------
constexpr int B_      = 8;
constexpr int NSEQ    = 4096;
constexpr int MTOK    = B_ * NSEQ;          // 32768
constexpr int D       = 512;
constexpr int DFF     = 2048;
constexpr int HEADS   = 8;
constexpr int HD      = 64;                 // head dim

// ---------------------------------------------------------------------------
// Scratch (static device globals -- allocation-free contract)
// ---------------------------------------------------------------------------
__device__ float g_seasonal[MTOK * D];        // fp32 residual stream
__device__ float g_trend   [MTOK * D];        // fp32 trend
__device__ float g_ln      [MTOK * D];        // fp32 LN1 output
__device__ float g_qkv     [MTOK * 3 * D];    // fp32 q(elu+1)|k(elu+1)|v, ld 1536
__device__ bf16  g_lnb     [MTOK * D];        // bf16 LN2 output
__device__ bf16  g_h       [MTOK * DFF];      // bf16 FFN hidden
__device__ float g_kvp     [4 * 64 * HD * HD];// 4 deterministic n-chunk partials of kv
__device__ bf16  g_Mhi     [B_ * D * D];      // (kv @ Wo) per batch, split hi
__device__ bf16  g_Mlo     [B_ * D * D];      //                      split lo
__device__ bf16  g_Wqkv_hi [D * 3 * D];
__device__ bf16  g_Wqkv_lo [D * 3 * D];
__device__ bf16  g_Wf1b    [D * DFF];
__device__ bf16  g_Wf2b    [DFF * D];
__device__ float g_bqkv    [3 * D];

__device__ __forceinline__ void split2(float x, bf16& hi, bf16& lo) {
    hi = __float2bfloat16(x);
    lo = __float2bfloat16(x - __bfloat162float(hi));
}

// ---------------------------------------------------------------------------
// 1. Weight conversion / splitting (tiny)
// ---------------------------------------------------------------------------
__global__ void convert_weights(const float* __restrict__ Wq, const float* __restrict__ Wk,
                                const float* __restrict__ Wv,
                                const float* __restrict__ bq, const float* __restrict__ bk,
                                const float* __restrict__ bv,
                                const float* __restrict__ Wf1, const float* __restrict__ Wf2) {
    int i = blockIdx.x * 256 + threadIdx.x;
    if (i < D * D) {
        int r = i >> 9, c = i & 511;
        size_t o = (size_t)r * (3 * D) + c;
        bf16 hi, lo;
        split2(Wq[i], hi, lo); g_Wqkv_hi[o]        = hi; g_Wqkv_lo[o]        = lo;
        split2(Wk[i], hi, lo); g_Wqkv_hi[o + 512]  = hi; g_Wqkv_lo[o + 512]  = lo;
        split2(Wv[i], hi, lo); g_Wqkv_hi[o + 1024] = hi; g_Wqkv_lo[o + 1024] = lo;
    }
    if (i < D * DFF) {
        g_Wf1b[i] = __float2bfloat16(Wf1[i]);
        g_Wf2b[i] = __float2bfloat16(Wf2[i]);
    }
    if (i < D) {
        g_bqkv[i]        = bq[i];
        g_bqkv[i + 512]  = bk[i];
        g_bqkv[i + 1024] = bv[i];
    }
}

// ---------------------------------------------------------------------------
// 2. Series decomposition + LayerNorm1 (fused, one block per token row)
// ---------------------------------------------------------------------------
__global__ void __launch_bounds__(256) decomp_ln1(const float* __restrict__ x,
                                                  const float* __restrict__ g1,
                                                  const float* __restrict__ b1) {
    int m = blockIdx.x;
    int n = m & (NSEQ - 1);
    const float* xr = x + (size_t)m * D;
    __shared__ float sse[D];
    __shared__ float red[16];
    __shared__ float s_mean, s_inv;
    int t = threadIdx.x;
    float sum = 0.f, sq = 0.f;
#pragma unroll
    for (int i = 0; i < 2; i++) {
        int c = t + i * 256;
        float x0 = xr[c];
        float xm = (n > 0)        ? xr[c - D] : 0.f;
        float xp = (n < NSEQ - 1) ? xr[c + D] : 0.f;
        float tr = (xm + x0 + xp) * (1.f / 3.f);
        float se = x0 - tr;
        g_trend[(size_t)m * D + c]    = tr;
        g_seasonal[(size_t)m * D + c] = se;
        sse[c] = se;
        sum += se; sq += se * se;
    }
#pragma unroll
    for (int o = 16; o > 0; o >>= 1) {
        sum += __shfl_xor_sync(0xffffffffu, sum, o);
        sq  += __shfl_xor_sync(0xffffffffu, sq,  o);
    }
    if ((t & 31) == 0) { red[t >> 5] = sum; red[8 + (t >> 5)] = sq; }
    __syncthreads();
    if (t == 0) {
        float S = 0.f, Q = 0.f;
#pragma unroll
        for (int w = 0; w < 8; w++) { S += red[w]; Q += red[8 + w]; }
        float mean = S * (1.f / (float)D);
        float var  = Q * (1.f / (float)D) - mean * mean;
        s_mean = mean;
        s_inv  = rsqrtf(var + 1e-5f);
    }
    __syncthreads();
#pragma unroll
    for (int i = 0; i < 2; i++) {
        int c = t + i * 256;
        float v = (sse[c] - s_mean) * s_inv * g1[c] + b1[c];
        g_ln[(size_t)m * D + c] = v;
    }
}

// ---------------------------------------------------------------------------
// 7. LayerNorm2 (seasonal -> bf16)
// ---------------------------------------------------------------------------
__global__ void __launch_bounds__(256) ln2_kernel(const float* __restrict__ g2,
                                                  const float* __restrict__ b2) {
    int m = blockIdx.x;
    const float* sr = g_seasonal + (size_t)m * D;
    __shared__ float sse[D];
    __shared__ float red[16];
    __shared__ float s_mean, s_inv;
    int t = threadIdx.x;
    float sum = 0.f, sq = 0.f;
#pragma unroll
    for (int i = 0; i < 2; i++) {
        int c = t + i * 256;
        float se = sr[c];
        sse[c] = se;
        sum += se; sq += se * se;
    }
#pragma unroll
    for (int o = 16; o > 0; o >>= 1) {
        sum += __shfl_xor_sync(0xffffffffu, sum, o);
        sq  += __shfl_xor_sync(0xffffffffu, sq,  o);
    }
    if ((t & 31) == 0) { red[t >> 5] = sum; red[8 + (t >> 5)] = sq; }
    __syncthreads();
    if (t == 0) {
        float S = 0.f, Q = 0.f;
#pragma unroll
        for (int w = 0; w < 8; w++) { S += red[w]; Q += red[8 + w]; }
        float mean = S * (1.f / (float)D);
        float var  = Q * (1.f / (float)D) - mean * mean;
        s_mean = mean;
        s_inv  = rsqrtf(var + 1e-5f);
    }
    __syncthreads();
#pragma unroll
    for (int i = 0; i < 2; i++) {
        int c = t + i * 256;
        float v = (sse[c] - s_mean) * s_inv * g2[c] + b2[c];
        g_lnb[(size_t)m * D + c] = __float2bfloat16(v);
    }
}

// ---------------------------------------------------------------------------
// 4. kv partials: kv[b,h,d,f] = sum_n k[b,n,h,d] * v[b,n,h,f]  (fp32 SIMT)
//    grid = 4 chunks * 64 (b,h); deterministic (no atomics)
// ---------------------------------------------------------------------------
__global__ void __launch_bounds__(256) kv_kernel() {
    int bh    = blockIdx.x & 63;
    int chunk = blockIdx.x >> 6;
    int b = bh >> 3, h = bh & 7;
    const float* kp = g_qkv + (size_t)b * NSEQ * 1536 + 512  + h * HD;
    const float* vp = g_qkv + (size_t)b * NSEQ * 1536 + 1024 + h * HD;
    __shared__ __align__(16) float sk[8][HD];
    __shared__ __align__(16) float sv[8][HD];
    int t = threadIdx.x;
    int d0 = (t >> 4) * 4, f0 = (t & 15) * 4;
    float acc[4][4] = {};
    int n0base = chunk * (NSEQ / 4);
    for (int n0 = n0base; n0 < n0base + NSEQ / 4; n0 += 8) {
#pragma unroll
        for (int i = 0; i < 2; i++) {
            int j = t + i * 256;
            int r = j >> 6, c = j & 63;
            sk[r][c] = kp[(size_t)(n0 + r) * 1536 + c];
            sv[r][c] = vp[(size_t)(n0 + r) * 1536 + c];
        }
        __syncthreads();
#pragma unroll
        for (int r = 0; r < 8; r++) {
            float4 k4 = *reinterpret_cast<const float4*>(&sk[r][d0]);
            float4 v4 = *reinterpret_cast<const float4*>(&sv[r][f0]);
            float kk[4] = {k4.x, k4.y, k4.z, k4.w};
            float vv[4] = {v4.x, v4.y, v4.z, v4.w};
#pragma unroll
            for (int i = 0; i < 4; i++)
#pragma unroll
                for (int j = 0; j < 4; j++) acc[i][j] += kk[i] * vv[j];
        }
        __syncthreads();
    }
    float* dst = g_kvp + (size_t)chunk * (64 * HD * HD) + (size_t)bh * (HD * HD);
#pragma unroll
    for (int i = 0; i < 4; i++)
#pragma unroll
        for (int j = 0; j < 4; j++) dst[(d0 + i) * HD + f0 + j] = acc[i][j];
}

// ---------------------------------------------------------------------------
// 5. M[b, h*64+d, j] = sum_f kv[b,h,d,f] * Wo[h*64+f, j]   (fp32, split out)
//    grid = 64 (b,h) * 4 j-tiles of 128
// ---------------------------------------------------------------------------
__global__ void __launch_bounds__(256) kvwo_kernel(const float* __restrict__ Wo) {
    int bh = blockIdx.x >> 2, jt = blockIdx.x & 3;
    int b = bh >> 3, h = bh & 7;
    __shared__ __align__(16) float skv[HD][HD];
    int t = threadIdx.x;
#pragma unroll
    for (int i = 0; i < 16; i++) {
        int idx = t + i * 256;
        float s = 0.f;
#pragma unroll
        for (int c = 0; c < 4; c++)
            s += g_kvp[(size_t)c * (64 * HD * HD) + (size_t)bh * (HD * HD) + idx];
        reinterpret_cast<float*>(skv)[idx] = s;
    }
    __syncthreads();
    int j0 = jt * 128;
    int d0 = (t >> 5) * 8;
    int jj = (t & 31) * 4;
    float acc[8][4] = {};
    for (int f = 0; f < HD; f++) {
        float4 w4 = *reinterpret_cast<const float4*>(&Wo[(size_t)(h * HD + f) * D + j0 + jj]);
        float w[4] = {w4.x, w4.y, w4.z, w4.w};
#pragma unroll
        for (int i = 0; i < 8; i++) {
            float kv = skv[d0 + i][f];
#pragma unroll
            for (int j = 0; j < 4; j++) acc[i][j] += kv * w[j];
        }
    }
#pragma unroll
    for (int i = 0; i < 8; i++)
#pragma unroll
        for (int j = 0; j < 4; j++) {
            size_t o = (size_t)b * (D * D) + (size_t)(h * HD + d0 + i) * D + j0 + jj + j;
            bf16 hi, lo;
            split2(acc[i][j], hi, lo);
            g_Mhi[o] = hi;
            g_Mlo[o] = lo;
        }
}

// ---------------------------------------------------------------------------
// Generic wmma GEMM (128x128x32 block, 8 warps of 64x32), fp32 accumulate.
// SPLIT sites use bf16x2 (hi/lo) for ~fp32-grade precision (3 MMA passes).
// ---------------------------------------------------------------------------
constexpr int BM = 128, BN = 128, BK = 32;
#define S_QKV  0
#define S_ATTN 1
#define S_FFN1 2
#define S_FFN2 3

template <int SITE>
__global__ void __launch_bounds__(256) gemm_kernel(const float* __restrict__ bias,
                                                   float* __restrict__ outp) {
    constexpr bool SPLIT = (SITE == S_QKV || SITE == S_ATTN);
    constexpr int K   = (SITE == S_FFN2) ? 2048 : 512;
    constexpr int LDA = (SITE == S_ATTN) ? 1536 : ((SITE == S_FFN2) ? 2048 : 512);
    constexpr int LDB = (SITE == S_QKV) ? 1536 : ((SITE == S_FFN1) ? 2048 : 512);

    __shared__ bf16 Ash[BM][BK + 8];
    __shared__ bf16 Asl[BM][BK + 8];
    __shared__ bf16 Bsh[BK][BN + 8];
    __shared__ bf16 Bsl[BK][BN + 8];
    __shared__ float stage[8][264];

    const float* Af = nullptr;
    const bf16*  Ab = nullptr;
    const bf16*  Bh = nullptr;
    const bf16*  Bl = nullptr;
    if constexpr (SITE == S_QKV)  { Af = g_ln;   Bh = g_Wqkv_hi; Bl = g_Wqkv_lo; }
    if constexpr (SITE == S_ATTN) { Af = g_qkv;  Bh = g_Mhi + (size_t)blockIdx.z * (D * D);
                                    Bl = g_Mlo + (size_t)blockIdx.z * (D * D); }
    if constexpr (SITE == S_FFN1) { Ab = g_lnb;  Bh = g_Wf1b; }
    if constexpr (SITE == S_FFN2) { Ab = g_h;    Bh = g_Wf2b; }

    int bm = blockIdx.y * BM + ((SITE == S_ATTN) ? blockIdx.z * NSEQ : 0);
    int bn = blockIdx.x * BN;
    int warp = threadIdx.x >> 5, lane = threadIdx.x & 31;
    int wmr = (warp >> 2) * 64;   // warp row base in tile
    int wnc = (warp & 3) * 32;    // warp col base in tile

    wm::fragment<wm::accumulator, 16, 16, 16, float> acc[4][2];
#pragma unroll
    for (int i = 0; i < 4; i++)
#pragma unroll
        for (int j = 0; j < 2; j++) wm::fill_fragment(acc[i][j], 0.f);

    for (int k0 = 0; k0 < K; k0 += BK) {
        // ---- load tiles to shared ----
        if constexpr (SPLIT) {
#pragma unroll
            for (int i = 0; i < 4; i++) {
                int v = threadIdx.x + i * 256;      // 1024 float4 covers 128x32 fp32
                int r = v >> 3, co = (v & 7) * 4;
                float4 a4 = *reinterpret_cast<const float4*>(Af + (size_t)(bm + r) * LDA + k0 + co);
                float av[4] = {a4.x, a4.y, a4.z, a4.w};
#pragma unroll
                for (int e = 0; e < 4; e++) {
                    bf16 hi = __float2bfloat16(av[e]);
                    Ash[r][co + e] = hi;
                    Asl[r][co + e] = __float2bfloat16(av[e] - __bfloat162float(hi));
                }
            }
        } else {
#pragma unroll
            for (int i = 0; i < 2; i++) {
                int v = threadIdx.x + i * 256;      // 512 uint4 covers 128x32 bf16
                int r = v >> 2, co = (v & 3) * 8;
                *reinterpret_cast<uint4*>(&Ash[r][co]) =
                    *reinterpret_cast<const uint4*>(Ab + (size_t)(bm + r) * LDA + k0 + co);
            }
        }
#pragma unroll
        for (int i = 0; i < 2; i++) {
            int v = threadIdx.x + i * 256;          // 512 uint4 covers 32x128 bf16
            int r = v >> 4, co = (v & 15) * 8;
            *reinterpret_cast<uint4*>(&Bsh[r][co]) =
                *reinterpret_cast<const uint4*>(Bh + (size_t)(k0 + r) * LDB + bn + co);
            if constexpr (SPLIT)
                *reinterpret_cast<uint4*>(&Bsl[r][co]) =
                    *reinterpret_cast<const uint4*>(Bl + (size_t)(k0 + r) * LDB + bn + co);
        }
        __syncthreads();

        // ---- compute ----
#pragma unroll
        for (int kk = 0; kk < BK; kk += 16) {
            wm::fragment<wm::matrix_a, 16, 16, 16, bf16, wm::row_major> ah[4];
            wm::fragment<wm::matrix_b, 16, 16, 16, bf16, wm::row_major> bhf[2];
#pragma unroll
            for (int i = 0; i < 4; i++)
                wm::load_matrix_sync(ah[i], &Ash[wmr + i * 16][kk], BK + 8);
#pragma unroll
            for (int j = 0; j < 2; j++)
                wm::load_matrix_sync(bhf[j], &Bsh[kk][wnc + j * 16], BN + 8);
#pragma unroll
            for (int i = 0; i < 4; i++)
#pragma unroll
                for (int j = 0; j < 2; j++)
                    wm::mma_sync(acc[i][j], ah[i], bhf[j], acc[i][j]);
            if constexpr (SPLIT) {
                wm::fragment<wm::matrix_b, 16, 16, 16, bf16, wm::row_major> blf[2];
#pragma unroll
                for (int j = 0; j < 2; j++)
                    wm::load_matrix_sync(blf[j], &Bsl[kk][wnc + j * 16], BN + 8);
#pragma unroll
                for (int i = 0; i < 4; i++)
#pragma unroll
                    for (int j = 0; j < 2; j++)
                        wm::mma_sync(acc[i][j], ah[i], blf[j], acc[i][j]);
                wm::fragment<wm::matrix_a, 16, 16, 16, bf16, wm::row_major> al[4];
#pragma unroll
                for (int i = 0; i < 4; i++)
                    wm::load_matrix_sync(al[i], &Asl[wmr + i * 16][kk], BK + 8);
#pragma unroll
                for (int i = 0; i < 4; i++)
#pragma unroll
                    for (int j = 0; j < 2; j++)
                        wm::mma_sync(acc[i][j], al[i], bhf[j], acc[i][j]);
            }
        }
        __syncthreads();
    }

    // ---- epilogue via per-warp smem staging ----
#pragma unroll
    for (int i = 0; i < 4; i++)
#pragma unroll
        for (int j = 0; j < 2; j++) {
            wm::store_matrix_sync(&stage[warp][0], acc[i][j], 16, wm::mem_row_major);
            __syncwarp();
#pragma unroll
            for (int l = 0; l < 8; l++) {
                int idx = lane + l * 32;
                int r = idx >> 4, c = idx & 15;
                int row = bm + wmr + i * 16 + r;
                int col = bn + wnc + j * 16 + c;
                float v = stage[warp][idx];
                if constexpr (SITE == S_QKV) {
                    v += g_bqkv[col];
                    if (col < 1024) v = (v > 0.f) ? (v + 1.f) : expf(v);   // elu+1
                    g_qkv[(size_t)row * 1536 + col] = v;
                } else if constexpr (SITE == S_ATTN) {
                    size_t o = (size_t)row * D + col;
                    g_seasonal[o] += v + bias[col];
                } else if constexpr (SITE == S_FFN1) {
                    v += bias[col];
                    v = 0.5f * v * (1.f + erff(v * 0.70710678118654752f));  // exact gelu
                    g_h[(size_t)row * DFF + col] = __float2bfloat16(v);
                } else {
                    size_t o = (size_t)row * D + col;
                    outp[o] = v + bias[col] + g_seasonal[o] + g_trend[o];
                }
            }
            __syncwarp();
        }
}

// ---------------------------------------------------------------------------
// Launch
// ---------------------------------------------------------------------------
extern "C" void kernel_launch(void* const* d_in, const int* in_sizes, int n_in,
                              void* d_out, int out_size) {
    (void)in_sizes; (void)n_in; (void)out_size;
    const float* x   = (const float*)d_in[0];
    const float* Wq  = (const float*)d_in[1];
    const float* bq  = (const float*)d_in[2];
    const float* Wk  = (const float*)d_in[3];
    const float* bk  = (const float*)d_in[4];
    const float* Wv  = (const float*)d_in[5];
    const float* bv  = (const float*)d_in[6];
    const float* Wo  = (const float*)d_in[7];
    const float* bo  = (const float*)d_in[8];
    const float* g1  = (const float*)d_in[9];
    const float* b1  = (const float*)d_in[10];
    const float* g2  = (const float*)d_in[11];
    const float* b2  = (const float*)d_in[12];
    const float* Wf1 = (const float*)d_in[13];
    const float* bf1 = (const float*)d_in[14];
    const float* Wf2 = (const float*)d_in[15];
    const float* bf2 = (const float*)d_in[16];
    float* out = (float*)d_out;

    convert_weights<<<4096, 256>>>(Wq, Wk, Wv, bq, bk, bv, Wf1, Wf2);
    decomp_ln1<<<MTOK, 256>>>(x, g1, b1);
    gemm_kernel<S_QKV><<<dim3(3 * D / BN, MTOK / BM, 1), 256>>>(nullptr, nullptr);
    kv_kernel<<<256, 256>>>();
    kvwo_kernel<<<256, 256>>>(Wo);
    gemm_kernel<S_ATTN><<<dim3(D / BN, NSEQ / BM, B_), 256>>>(bo, nullptr);
    ln2_kernel<<<MTOK, 256>>>(g2, b2);
    gemm_kernel<S_FFN1><<<dim3(DFF / BN, MTOK / BM, 1), 256>>>(bf1, nullptr);
    gemm_kernel<S_FFN2><<<dim3(D / BN, MTOK / BM, 1), 256>>>(bf2, out);
}